// round 7
// baseline (speedup 1.0000x reference)
#include <cuda_runtime.h>
#include <cuda_bf16.h>

// Problem constants: x,y [4096, 16, 128] f32, out [4096, 99, 128] f32.
#define N_EDGES   4096
#define DIM_IN    16
#define DIM_OUT   99
#define CHANNELS  128
#define VGROUPS   (CHANNELS / 4)   // 32 float4 groups (= warp width)
#define NNZ_CAP   1024

#define NWARPS    8
#define NTHREADS  (NWARPS * 32)    // 256
#define NSLOTS    4                // path slots per warp (23 paths fit in 32)
#define MAX_PATHS 32
#define MAX_PE    96               // max entries per path

// Packed CG entries, grouped by path, sorted by (m1, m2) within a path.
//  .x bits: [0:4) mu1, [4:8) mu2, [8:11) acc index (mu3 - path_k0),
//           [11] new-m1 flag (load a), [12] new-pair flag (load b, recompute ab)
//  .y: cg float bits
__device__ int2 g_ent[NNZ_CAP];
// Per (warp, slot) work item: {entry_beg, entry_end, out_row_base, n_rows}
__device__ int4 g_work[NWARPS * NSLOTS];

__device__ __forceinline__ int blk_of(int m) {   // irrep block of input index
    return (m < 1) ? 0 : (m < 4) ? 1 : (m < 9) ? 2 : 3;
}

// Deterministic single-block build:
//  1) per output row: owning (l1,l2) group id (from any entry's mu1/mu2 blocks)
//  2) split contiguous gid-runs into paths (run length 1/3/5/7 single; 6=1+5; 10=3+7)
//  3) per-path entry counts + prefix, serpentine load-balance over warp slots
//  4) per path: collect entries, stable-sort by (mu1,mu2), emit packed w/ flags
__global__ void build_csr_kernel(const int* __restrict__ mu1,
                                 const int* __restrict__ mu2,
                                 const int* __restrict__ mu3,
                                 const float* __restrict__ cg,
                                 int nnz)
{
    __shared__ int   s1[NNZ_CAP];
    __shared__ int   s2[NNZ_CAP];
    __shared__ int   s3[NNZ_CAP];
    __shared__ float sc[NNZ_CAP];
    __shared__ int   row_gid[DIM_OUT];
    __shared__ int   p_k0[MAX_PATHS], p_nr[MAX_PATHS], p_cnt[MAX_PATHS], p_base[MAX_PATHS];
    __shared__ int   s_np;

    const int tid = threadIdx.x;
    const int nt  = blockDim.x;

    for (int j = tid; j < nnz; j += nt) {
        s1[j] = mu1[j];
        s2[j] = mu2[j];
        s3[j] = mu3[j];
        sc[j] = cg[j];
    }
    __syncthreads();

    if (tid < DIM_OUT) {
        int g = 0;
        for (int j = 0; j < nnz; ++j) {
            if (s3[j] == tid) { g = blk_of(s1[j]) * 4 + blk_of(s2[j]); break; }
        }
        row_gid[tid] = g;
    }
    __syncthreads();

    if (tid == 0) {
        int np = 0, k = 0;
        while (k < DIM_OUT) {
            const int g = row_gid[k];
            int L = 0;
            while (k + L < DIM_OUT && row_gid[k + L] == g) ++L;
            int sizes[3]; int ns;
            if (L == 1 || L == 3 || L == 5 || L == 7) { sizes[0] = L; ns = 1; }
            else if (L == 6)  { sizes[0] = 1; sizes[1] = 5; ns = 2; }
            else if (L == 10) { sizes[0] = 3; sizes[1] = 7; ns = 2; }
            else if (L == 4)  { sizes[0] = 1; sizes[1] = 3; ns = 2; }
            else if (L == 8)  { sizes[0] = 3; sizes[1] = 5; ns = 2; }
            else              { sizes[0] = L; ns = 1; }   // last-resort fallback
            int kk = k;
            for (int i = 0; i < ns && np < MAX_PATHS; ++i) {
                p_k0[np] = kk; p_nr[np] = sizes[i]; kk += sizes[i]; ++np;
            }
            k += L;
        }
        s_np = np;
    }
    __syncthreads();
    const int np = s_np;

    if (tid < np) {
        const int k0 = p_k0[tid], k1 = k0 + p_nr[tid];
        int c = 0;
        for (int j = 0; j < nnz; ++j) c += (s3[j] >= k0 && s3[j] < k1);
        p_cnt[tid] = c;
    }
    __syncthreads();

    if (tid == 0) {
        int acc = 0;
        for (int p = 0; p < np; ++p) { p_base[p] = acc; acc += p_cnt[p]; }

        // serpentine balance: sort paths by entry count desc, deal to warps
        int ord[MAX_PATHS];
        for (int p = 0; p < np; ++p) ord[p] = p;
        for (int a = 1; a < np; ++a) {
            int v = ord[a]; int b = a - 1;
            while (b >= 0 && p_cnt[ord[b]] < p_cnt[v]) { ord[b + 1] = ord[b]; --b; }
            ord[b + 1] = v;
        }
        for (int s = 0; s < NWARPS * NSLOTS; ++s) g_work[s] = make_int4(0, 0, 0, 0);
        int slotc[NWARPS];
        for (int w = 0; w < NWARPS; ++w) slotc[w] = 0;
        for (int i = 0; i < np; ++i) {
            const int pass = i / NWARPS, pos = i % NWARPS;
            const int w = (pass & 1) ? (NWARPS - 1 - pos) : pos;
            const int p = ord[i];
            if (slotc[w] < NSLOTS) {
                g_work[w * NSLOTS + slotc[w]] =
                    make_int4(p_base[p], p_base[p] + p_cnt[p], p_k0[p], p_nr[p]);
                slotc[w]++;
            }
        }
    }
    __syncthreads();

    if (tid < np) {
        const int k0 = p_k0[tid], k1 = k0 + p_nr[tid], base = p_base[tid];
        int idx[MAX_PE];
        int cnt = 0;
        for (int j = 0; j < nnz; ++j)
            if (s3[j] >= k0 && s3[j] < k1 && cnt < MAX_PE) idx[cnt++] = j;
        // stable insertion sort by (mu1, mu2); original j-order kept within ties
        for (int a = 1; a < cnt; ++a) {
            const int ja = idx[a];
            const int key = s1[ja] * 16 + s2[ja];
            int b = a - 1;
            while (b >= 0 && (s1[idx[b]] * 16 + s2[idx[b]]) > key) {
                idx[b + 1] = idx[b]; --b;
            }
            idx[b + 1] = ja;
        }
        int prev1 = -1, prev2 = -1;
        for (int p = 0; p < cnt; ++p) {
            const int j  = idx[p];
            const int na = (s1[j] != prev1) ? 1 : 0;
            const int nb = (na || s2[j] != prev2) ? 1 : 0;
            g_ent[base + p] = make_int2(s1[j] | (s2[j] << 4) | ((s3[j] - k0) << 8) |
                                        (na << 11) | (nb << 12),
                                        __float_as_int(sc[j]));
            prev1 = s1[j]; prev2 = s2[j];
        }
    }
}

#define FMA4(d, c, v) \
    d.x = fmaf(c, v.x, d.x); d.y = fmaf(c, v.y, d.y); \
    d.z = fmaf(c, v.z, d.z); d.w = fmaf(c, v.w, d.w)

// Main kernel: one block per edge, 8 warps. Warp w processes up to NSLOTS
// paths; per path it keeps all (<=7) row accumulators in registers and reloads
// shared operands only when m1 / (m1,m2) change (sorted entry stream).
// Every one of the 99 output rows belongs to exactly one path and is written
// exactly once (rows of empty paths get zeros).
__global__ __launch_bounds__(NTHREADS)
void tp_main_kernel(const float4* __restrict__ x,
                    const float4* __restrict__ y,
                    float4* __restrict__ out)
{
    __shared__ float4 xs[DIM_IN * VGROUPS];   // 8 KB
    __shared__ float4 ys[DIM_IN * VGROUPS];   // 8 KB

    const int n    = blockIdx.x;
    const int tid  = threadIdx.x;
    const int w    = tid >> 5;
    const int lane = tid & 31;

    const float4* xb = x + (size_t)n * (DIM_IN * VGROUPS);
    const float4* yb = y + (size_t)n * (DIM_IN * VGROUPS);
#pragma unroll
    for (int i = tid; i < DIM_IN * VGROUPS; i += NTHREADS) {
        xs[i] = xb[i];
        ys[i] = yb[i];
    }
    __syncthreads();

    const char* xc = (const char*)xs + lane * 16;
    const char* yc = (const char*)ys + lane * 16;

    float4* ob = out + (size_t)n * (DIM_OUT * VGROUPS) + lane;

#pragma unroll
    for (int slot = 0; slot < NSLOTS; ++slot) {
        const int4 wk = __ldg(&g_work[w * NSLOTS + slot]);
        const int beg = wk.x, end = wk.y, k0 = wk.z, nr = wk.w;
        if (nr == 0) continue;

        float4 acc0 = make_float4(0.f,0.f,0.f,0.f), acc1 = acc0, acc2 = acc0,
               acc3 = acc0, acc4 = acc0, acc5 = acc0, acc6 = acc0;
        float4 a  = make_float4(0.f,0.f,0.f,0.f);
        float4 ab = a;

        int2 e = (beg < end) ? __ldg(&g_ent[beg]) : make_int2(0, 0);
        for (int j = beg; j < end; ++j) {
            const int2 en = (j + 1 < end) ? __ldg(&g_ent[j + 1]) : e;  // prefetch
            const int  m  = e.x;
            if (m & (1 << 11))
                a = *(const float4*)(xc + ((m & 15) << 9));
            if (m & (1 << 12)) {
                const float4 b = *(const float4*)(yc + (((m >> 4) & 15) << 9));
                ab.x = a.x * b.x; ab.y = a.y * b.y;
                ab.z = a.z * b.z; ab.w = a.w * b.w;
            }
            const float c = __int_as_float(e.y);
            switch ((m >> 8) & 7) {              // warp-uniform
                case 0: FMA4(acc0, c, ab); break;
                case 1: FMA4(acc1, c, ab); break;
                case 2: FMA4(acc2, c, ab); break;
                case 3: FMA4(acc3, c, ab); break;
                case 4: FMA4(acc4, c, ab); break;
                case 5: FMA4(acc5, c, ab); break;
                default: FMA4(acc6, c, ab); break;
            }
            e = en;
        }

        // one coalesced 512B store per row; compile-time acc indices
        float4* po = ob + (size_t)k0 * VGROUPS;
        po[0] = acc0;
        if (nr > 1) po[1 * VGROUPS] = acc1;
        if (nr > 2) po[2 * VGROUPS] = acc2;
        if (nr > 3) po[3 * VGROUPS] = acc3;
        if (nr > 4) po[4 * VGROUPS] = acc4;
        if (nr > 5) po[5 * VGROUPS] = acc5;
        if (nr > 6) po[6 * VGROUPS] = acc6;
    }
}

extern "C" void kernel_launch(void* const* d_in, const int* in_sizes, int n_in,
                              void* d_out, int out_size)
{
    const float* x   = (const float*)d_in[0];
    const float* y   = (const float*)d_in[1];
    const int*   mu1 = (const int*)  d_in[2];
    const int*   mu2 = (const int*)  d_in[3];
    const int*   mu3 = (const int*)  d_in[4];
    const float* cg  = (const float*)d_in[5];

    int nnz = in_sizes[5];
    if (nnz > NNZ_CAP) nnz = NNZ_CAP;

    build_csr_kernel<<<1, 1024>>>(mu1, mu2, mu3, cg, nnz);

    tp_main_kernel<<<N_EDGES, NTHREADS>>>((const float4*)x,
                                          (const float4*)y,
                                          (float4*)d_out);
}

// round 8
// speedup vs baseline: 1.8730x; 1.8730x over previous
#include <cuda_runtime.h>
#include <cuda_bf16.h>

// Problem constants: x,y [4096, 16, 128] f32, out [4096, 99, 128] f32.
#define N_EDGES   4096
#define DIM_IN    16
#define DIM_OUT   99
#define CHANNELS  128
#define VGROUPS   (CHANNELS / 4)   // 32 float4 groups (= warp width)
#define NNZ_CAP   1024

#define NWARPS    9
#define NTHREADS  (NWARPS * 32)    // 288
#define ROWS_PER_WARP 11           // 9 * 11 = 99

// Compact CSR of the CG metadata (rows in natural order, which is already
// mu1-ascending within a row — np.nonzero emits lexicographic (i1,i2,i3)).
//  entry.x: bit0          = "same mu1 as previous entry in this row" (skip x reload)
//           bits [1..15]  = mu1*512  (byte offset of x float4 row)
//           bits [16..31] = mu2*512  (byte offset of y float4 row)
//  entry.y: cg float bits
__device__ int  g_off[DIM_OUT + 1];
__device__ int2 g_ent[NNZ_CAP];

// Fast deterministic build: stage COO in shared; 99 threads count their row
// (lockstep broadcast scans); serial prefix; single-pass per-row emit in
// natural j-order with consecutive-mu1 reuse flag. No sorts, no local arrays.
__global__ void build_csr_kernel(const int* __restrict__ mu1,
                                 const int* __restrict__ mu2,
                                 const int* __restrict__ mu3,
                                 const float* __restrict__ cg,
                                 int nnz)
{
    __shared__ int   s1[NNZ_CAP];
    __shared__ int   s3[NNZ_CAP];
    __shared__ int   s2c[NNZ_CAP];     // packed mu2 | cg is kept separate below
    __shared__ float sc[NNZ_CAP];
    __shared__ int   s_off[DIM_OUT + 1];

    const int tid = threadIdx.x;
    const int nt  = blockDim.x;

    for (int j = tid; j < nnz; j += nt) {
        s1[j]  = mu1[j];
        s2c[j] = mu2[j];
        s3[j]  = mu3[j];
        sc[j]  = cg[j];
    }
    __syncthreads();

    // per-row counts (each lane scans all nnz; s3[j] is a broadcast LDS read)
    if (tid < DIM_OUT) {
        int c = 0;
        for (int j = 0; j < nnz; ++j) c += (s3[j] == tid);
        s_off[tid + 1] = c;
    }
    __syncthreads();

    if (tid == 0) {
        s_off[0] = 0;
        for (int k = 0; k < DIM_OUT; ++k) s_off[k + 1] += s_off[k];
    }
    __syncthreads();

    if (tid <= DIM_OUT) g_off[tid] = s_off[tid];

    // per-row emit in natural order (already mu1-ascending within the row)
    if (tid < DIM_OUT) {
        int pos  = s_off[tid];
        int prev = -1;
        for (int j = 0; j < nnz; ++j) {
            if (s3[j] == tid) {
                const int m1 = s1[j];
                const int fl = (m1 == prev) ? 1 : 0;
                prev = m1;
                g_ent[pos++] = make_int2((m1 * 512) | fl | ((s2c[j] * 512) << 16),
                                         __float_as_int(sc[j]));
            }
        }
    }
}

// Main kernel (best-known config): one block per edge, 288 threads = 9 warps.
// Warp w owns rows k = w + 9r, r = 0..10 (interleaved for load balance);
// lanes span the 32 float4 channel groups. Metadata via uniform __ldg
// broadcast (L1-hot, keeps the LDS crossbar for operands only). x operand is
// reloaded only when mu1 changes (warp-uniform flag). Every output vector is
// written exactly once (empty rows write zeros) -> no output pre-zeroing.
__global__ __launch_bounds__(NTHREADS)
void tp_main_kernel(const float4* __restrict__ x,
                    const float4* __restrict__ y,
                    float4* __restrict__ out)
{
    __shared__ float4 xs[DIM_IN * VGROUPS];   // 8 KB
    __shared__ float4 ys[DIM_IN * VGROUPS];   // 8 KB
    __shared__ int    so[DIM_OUT + 1];

    const int n    = blockIdx.x;
    const int tid  = threadIdx.x;
    const int w    = tid >> 5;
    const int lane = tid & 31;

    const float4* xb = x + (size_t)n * (DIM_IN * VGROUPS);
    const float4* yb = y + (size_t)n * (DIM_IN * VGROUPS);
    for (int i = tid; i < DIM_IN * VGROUPS; i += NTHREADS) {
        xs[i] = xb[i];
        ys[i] = yb[i];
    }
    if (tid <= DIM_OUT) so[tid] = g_off[tid];
    __syncthreads();

    const char* xc = (const char*)xs + lane * 16;
    const char* yc = (const char*)ys + lane * 16;

    float4* ob = out + (size_t)n * (DIM_OUT * VGROUPS) + lane;

#pragma unroll
    for (int r = 0; r < ROWS_PER_WARP; ++r) {
        const int k   = w + NWARPS * r;       // uniform per warp
        const int beg = so[k];
        const int end = so[k + 1];

        float4 acc = make_float4(0.f, 0.f, 0.f, 0.f);
        float4 a   = make_float4(0.f, 0.f, 0.f, 0.f);

#pragma unroll 4
        for (int j = beg; j < end; ++j) {
            const int2  e = __ldg(&g_ent[j]); // uniform broadcast, L1-hot
            const float c = __int_as_float(e.y);
            if (!(e.x & 1))                   // warp-uniform: reload x only on new mu1
                a = *(const float4*)(xc + (e.x & 0xfffe));
            const float4 b = *(const float4*)(yc + ((unsigned)e.x >> 16));
            acc.x = fmaf(c * a.x, b.x, acc.x);
            acc.y = fmaf(c * a.y, b.y, acc.y);
            acc.z = fmaf(c * a.z, b.z, acc.z);
            acc.w = fmaf(c * a.w, b.w, acc.w);
        }
        ob[(size_t)k * VGROUPS] = acc;
    }
}

extern "C" void kernel_launch(void* const* d_in, const int* in_sizes, int n_in,
                              void* d_out, int out_size)
{
    const float* x   = (const float*)d_in[0];
    const float* y   = (const float*)d_in[1];
    const int*   mu1 = (const int*)  d_in[2];
    const int*   mu2 = (const int*)  d_in[3];
    const int*   mu3 = (const int*)  d_in[4];
    const float* cg  = (const float*)d_in[5];

    int nnz = in_sizes[5];
    if (nnz > NNZ_CAP) nnz = NNZ_CAP;

    build_csr_kernel<<<1, 256>>>(mu1, mu2, mu3, cg, nnz);

    tp_main_kernel<<<N_EDGES, NTHREADS>>>((const float4*)x,
                                          (const float4*)y,
                                          (float4*)d_out);
}

// round 12
// speedup vs baseline: 2.2315x; 1.1914x over previous
#include <cuda_runtime.h>
#include <cuda_bf16.h>

// Problem constants: x,y [4096, 16, 128] f32, out [4096, 99, 128] f32.
#define N_EDGES   4096
#define DIM_IN    16
#define DIM_OUT   99
#define CHANNELS  128
#define VGROUPS   (CHANNELS / 4)   // 32 float4 groups (= warp width)
#define NNZ_CAP   1024
#define NCHUNK    (NNZ_CAP / 32)   // 32 bitmask chunks

#define NWARPS    9
#define NTHREADS  (NWARPS * 32)    // 288
#define ROWS_PER_WARP 11           // 9 * 11 = 99

// Compact CSR of the CG metadata (entries in original j-order within each row,
// which is already mu1-ascending — np.nonzero emits lexicographic (i1,i2,i3)).
//  entry.x: bit0          = "same mu1 as previous entry in this row" (skip x reload)
//           bits [1..15]  = mu1*512  (byte offset of x float4 row)
//           bits [16..31] = mu2*512  (byte offset of y float4 row)
//  entry.y: cg float bits
__device__ int  g_off[DIM_OUT + 1];
__device__ int2 g_ent[NNZ_CAP];

// Fully parallel deterministic build (single block, 1024 threads, no serial
// row scans): per-row occupancy bitmasks via atomicOr (order-independent =>
// deterministic), ranks via prefix popcounts, reuse flag via previous-set-bit.
__global__ void build_csr_kernel(const int* __restrict__ mu1,
                                 const int* __restrict__ mu2,
                                 const int* __restrict__ mu3,
                                 const float* __restrict__ cg,
                                 int nnz)
{
    __shared__ int      s1[NNZ_CAP];
    __shared__ int      s3[NNZ_CAP];
    __shared__ unsigned msk[DIM_OUT][NCHUNK];     // 12.4 KB
    __shared__ int      pref[DIM_OUT][NCHUNK];    // 12.4 KB (exclusive chunk prefix)
    __shared__ int      s_off[DIM_OUT + 1];

    const int tid = threadIdx.x;
    const int nt  = blockDim.x;

    for (int i = tid; i < DIM_OUT * NCHUNK; i += nt)
        (&msk[0][0])[i] = 0u;
    __syncthreads();

    for (int j = tid; j < nnz; j += nt) {
        const int k = mu3[j];
        s3[j] = k;
        s1[j] = mu1[j];
        atomicOr(&msk[k][j >> 5], 1u << (j & 31));
    }
    __syncthreads();

    // per-row exclusive chunk-prefix popcounts (32 iterations, 99 threads)
    if (tid < DIM_OUT) {
        int acc = 0;
#pragma unroll
        for (int c = 0; c < NCHUNK; ++c) {
            pref[tid][c] = acc;
            acc += __popc(msk[tid][c]);
        }
        s_off[tid + 1] = acc;
    }
    __syncthreads();

    if (tid == 0) {
        s_off[0] = 0;
        for (int k = 0; k < DIM_OUT; ++k) s_off[k + 1] += s_off[k];
    }
    __syncthreads();

    if (tid <= DIM_OUT) g_off[tid] = s_off[tid];

    // scatter: rank from popcounts; flag from previous set bit's mu1
    for (int j = tid; j < nnz; j += nt) {
        const int k = s3[j];
        const int c = j >> 5, b = j & 31;
        const unsigned below = msk[k][c] & ((1u << b) - 1u);
        const int rank = pref[k][c] + __popc(below);

        int prev = -1;
        {
            unsigned m = below;
            int cc = c;
            while (m == 0u && cc > 0) m = msk[k][--cc];
            if (m) prev = cc * 32 + (31 - __clz(m));
        }
        const int m1 = s1[j];
        const int fl = (prev >= 0 && s1[prev] == m1) ? 1 : 0;

        g_ent[s_off[k] + rank] =
            make_int2((m1 * 512) | fl | ((mu2[j] * 512) << 16),
                      __float_as_int(cg[j]));
    }
}

// Main kernel (frozen best config): one block per edge, 288 threads = 9 warps.
// Warp w owns rows k = w + 9r, r = 0..10 (interleaved for load balance);
// lanes span the 32 float4 channel groups. Metadata via uniform __ldg
// broadcast (L1-hot, keeps the LDS crossbar for operands only). x operand is
// reloaded only when mu1 changes (warp-uniform flag). Every output vector is
// written exactly once (empty rows write zeros) -> no output pre-zeroing.
__global__ __launch_bounds__(NTHREADS)
void tp_main_kernel(const float4* __restrict__ x,
                    const float4* __restrict__ y,
                    float4* __restrict__ out)
{
    __shared__ float4 xs[DIM_IN * VGROUPS];   // 8 KB
    __shared__ float4 ys[DIM_IN * VGROUPS];   // 8 KB
    __shared__ int    so[DIM_OUT + 1];

    const int n    = blockIdx.x;
    const int tid  = threadIdx.x;
    const int w    = tid >> 5;
    const int lane = tid & 31;

    const float4* xb = x + (size_t)n * (DIM_IN * VGROUPS);
    const float4* yb = y + (size_t)n * (DIM_IN * VGROUPS);
    for (int i = tid; i < DIM_IN * VGROUPS; i += NTHREADS) {
        xs[i] = xb[i];
        ys[i] = yb[i];
    }
    if (tid <= DIM_OUT) so[tid] = g_off[tid];
    __syncthreads();

    const char* xc = (const char*)xs + lane * 16;
    const char* yc = (const char*)ys + lane * 16;

    float4* ob = out + (size_t)n * (DIM_OUT * VGROUPS) + lane;

#pragma unroll
    for (int r = 0; r < ROWS_PER_WARP; ++r) {
        const int k   = w + NWARPS * r;       // uniform per warp
        const int beg = so[k];
        const int end = so[k + 1];

        float4 acc = make_float4(0.f, 0.f, 0.f, 0.f);
        float4 a   = make_float4(0.f, 0.f, 0.f, 0.f);

#pragma unroll 4
        for (int j = beg; j < end; ++j) {
            const int2  e = __ldg(&g_ent[j]); // uniform broadcast, L1-hot
            const float c = __int_as_float(e.y);
            if (!(e.x & 1))                   // warp-uniform: reload x only on new mu1
                a = *(const float4*)(xc + (e.x & 0xfffe));
            const float4 b = *(const float4*)(yc + ((unsigned)e.x >> 16));
            acc.x = fmaf(c * a.x, b.x, acc.x);
            acc.y = fmaf(c * a.y, b.y, acc.y);
            acc.z = fmaf(c * a.z, b.z, acc.z);
            acc.w = fmaf(c * a.w, b.w, acc.w);
        }
        ob[(size_t)k * VGROUPS] = acc;
    }
}

extern "C" void kernel_launch(void* const* d_in, const int* in_sizes, int n_in,
                              void* d_out, int out_size)
{
    const float* x   = (const float*)d_in[0];
    const float* y   = (const float*)d_in[1];
    const int*   mu1 = (const int*)  d_in[2];
    const int*   mu2 = (const int*)  d_in[3];
    const int*   mu3 = (const int*)  d_in[4];
    const float* cg  = (const float*)d_in[5];

    int nnz = in_sizes[5];
    if (nnz > NNZ_CAP) nnz = NNZ_CAP;

    build_csr_kernel<<<1, 1024>>>(mu1, mu2, mu3, cg, nnz);

    tp_main_kernel<<<N_EDGES, NTHREADS>>>((const float4*)x,
                                          (const float4*)y,
                                          (float4*)d_out);
}